// round 2
// baseline (speedup 1.0000x reference)
#include <cuda_runtime.h>
#include <cuda_bf16.h>
#include <cstdint>

// ============================================================================
// HardMemory: per-pixel cosine-sim argmax over memory bank + threshold mask.
//   x: [32, 512, 64, 64] f32, memory: [1024, 512] f32, out like x.
// Identity: mask_n = (max_m dot(x_n, memnorm_m) > 0.8 * max(||x_n||, eps));
//           out = mask ? memory[argmax] : 0.  If mask=0, argmax irrelevant.
// bf16 mma.sync GEMM screens with margin; rare flagged pixels re-checked fp32.
// Family-portable PTX only (harness targets compute_103, no 'a' features).
// ============================================================================

#define THRESH  0.8f
#define CDIM    512
#define HWDIM   4096
#define MMEM    1024
#define TILE_PX 128
#define CHUNK_M 128
#define KTILE   64
#define NTILES  64        // 8 chunks * 8 k-tiles

// Prepass output: normalized memory rows, bf16, plain row-major [1024][512]
__device__ __align__(16) unsigned char g_membf[MMEM * CDIM * 2];

// ---------------------------------------------------------------------------
// smem layout (bytes)
// ---------------------------------------------------------------------------
#define SM_X     0                      // x tile [512 k][256B] bf16 = 131072
#define SM_B     131072                 // 2 x [128 m][128B] memnorm = 32768
#define SM_N2    (SM_B + 32768)         // 128 f32 ||x||^2
#define SM_RM    (SM_N2 + 512)          // 2*128 f32 per-warprow max
#define SM_RI    (SM_RM + 1024)         // 2*128 i32
#define SM_FLAG  (SM_RI + 1024)         // 128 i32
#define SM_PASS  (SM_FLAG + 512)        // 128 i32
#define SM_IDX   (SM_PASS + 512)        // 128 i32
#define SM_XV    (SM_IDX + 512)         // 512 f32 (exact-path staging)
#define SM_BESTU (SM_XV + 2048)         // u32
#define SM_BESTI (SM_BESTU + 4)         // i32
#define SM_TOTAL (SM_BESTI + 60)

// ---------------------------------------------------------------------------
__device__ __forceinline__ uint32_t smem_u32(const void* p) {
    uint32_t a;
    asm("{ .reg .u64 t; cvta.to.shared.u64 t, %1; cvt.u32.u64 %0, t; }"
        : "=r"(a) : "l"(p));
    return a;
}

__device__ __forceinline__ void cp_async16(uint32_t dst, const void* src) {
    asm volatile("cp.async.cg.shared.global [%0], [%1], 16;"
                 :: "r"(dst), "l"(src) : "memory");
}
#define CP_COMMIT() asm volatile("cp.async.commit_group;" ::: "memory")
#define CP_WAIT(N)  asm volatile("cp.async.wait_group %0;" :: "n"(N) : "memory")

__device__ __forceinline__ void ldsm_x4(uint32_t& r0, uint32_t& r1,
                                        uint32_t& r2, uint32_t& r3, uint32_t a) {
    asm volatile("ldmatrix.sync.aligned.m8n8.x4.shared.b16 {%0,%1,%2,%3}, [%4];"
                 : "=r"(r0), "=r"(r1), "=r"(r2), "=r"(r3) : "r"(a));
}
__device__ __forceinline__ void ldsm_x4t(uint32_t& r0, uint32_t& r1,
                                         uint32_t& r2, uint32_t& r3, uint32_t a) {
    asm volatile("ldmatrix.sync.aligned.m8n8.x4.trans.shared.b16 {%0,%1,%2,%3}, [%4];"
                 : "=r"(r0), "=r"(r1), "=r"(r2), "=r"(r3) : "r"(a));
}
__device__ __forceinline__ void mma16816(float& d0, float& d1, float& d2, float& d3,
                                         uint32_t a0, uint32_t a1, uint32_t a2, uint32_t a3,
                                         uint32_t b0, uint32_t b1) {
    asm volatile(
        "mma.sync.aligned.m16n8k16.row.col.f32.bf16.bf16.f32 "
        "{%0,%1,%2,%3}, {%4,%5,%6,%7}, {%8,%9}, {%0,%1,%2,%3};"
        : "+f"(d0), "+f"(d1), "+f"(d2), "+f"(d3)
        : "r"(a0), "r"(a1), "r"(a2), "r"(a3), "r"(b0), "r"(b1));
}

// ---------------------------------------------------------------------------
// Prepass: memnorm = memory / max(||row||, eps) -> bf16 row-major
// ---------------------------------------------------------------------------
__global__ __launch_bounds__(128) void normalize_mem_kernel(const float* __restrict__ memory) {
    const int m = blockIdx.x, tid = threadIdx.x;
    const float4 v = *(const float4*)(memory + (size_t)m * CDIM + tid * 4);
    float ss = v.x * v.x + v.y * v.y + v.z * v.z + v.w * v.w;
    #pragma unroll
    for (int o = 16; o > 0; o >>= 1) ss += __shfl_xor_sync(0xffffffffu, ss, o);
    __shared__ float ws[4];
    if ((tid & 31) == 0) ws[tid >> 5] = ss;
    __syncthreads();
    const float s = 1.0f / fmaxf(sqrtf(ws[0] + ws[1] + ws[2] + ws[3]), 1e-12f);
    uint32_t p0 = __bfloat16_as_ushort(__float2bfloat16(v.x * s)) |
                  ((uint32_t)__bfloat16_as_ushort(__float2bfloat16(v.y * s)) << 16);
    uint32_t p1 = __bfloat16_as_ushort(__float2bfloat16(v.z * s)) |
                  ((uint32_t)__bfloat16_as_ushort(__float2bfloat16(v.w * s)) << 16);
    *(uint2*)(g_membf + (size_t)m * (CDIM * 2) + tid * 8) = make_uint2(p0, p1);
}

// ---------------------------------------------------------------------------
// Main kernel
// ---------------------------------------------------------------------------
__global__ __launch_bounds__(256, 1) void hardmem_main_kernel(
    const float* __restrict__ x,
    const float* __restrict__ memory,
    float* __restrict__ out)
{
    extern __shared__ char smem[];
    const uint32_t smx = smem_u32(smem);
    const int tid = threadIdx.x;
    const int lane = tid & 31;
    const int wid = tid >> 5;
    const int warp_m = wid >> 2;        // 0..1  (64 mem rows each within chunk)
    const int warp_n = wid & 3;         // 0..3  (32 px each)
    const int b  = blockIdx.x >> 5;
    const int n0 = (blockIdx.x & 31) << 7;

    float* s_n2   = (float*)(smem + SM_N2);
    float* s_rm   = (float*)(smem + SM_RM);
    int*   s_ri   = (int*)(smem + SM_RI);
    int*   s_flag = (int*)(smem + SM_FLAG);
    int*   s_pass = (int*)(smem + SM_PASS);
    int*   s_idx  = (int*)(smem + SM_IDX);
    float* s_xv   = (float*)(smem + SM_XV);
    unsigned* s_bestu = (unsigned*)(smem + SM_BESTU);
    int*      s_besti = (int*)(smem + SM_BESTI);

    if (tid < TILE_PX) s_n2[tid] = 0.0f;

    // ---- prefetch memnorm tile 0 (chunk 0, kt 0) into buffer 0 ----
    {
        #pragma unroll
        for (int i = 0; i < 4; ++i) {
            const int j = tid + i * 256;          // granule: m = j/8, g = j%8
            const int m = j >> 3, g = j & 7;
            cp_async16(smx + SM_B + m * 128 + ((g * 16) ^ ((m & 7) * 16)),
                       g_membf + (size_t)m * 1024 + g * 16);
        }
        CP_COMMIT();
    }

    // ---- load resident x tile: [512 k][128 px] bf16 (k-major, no transpose) ----
    {
        const float* xb = x + (size_t)b * CDIM * HWDIM + n0;
        const int px4 = (lane << 2);                 // fixed 4 pixels per thread
        float ss0 = 0.f, ss1 = 0.f, ss2 = 0.f, ss3 = 0.f;
        #pragma unroll 8
        for (int it = 0; it < 64; ++it) {
            const int k = (tid >> 5) + it * 8;
            const float4 v = *(const float4*)(xb + (size_t)k * HWDIM + px4);
            ss0 += v.x * v.x; ss1 += v.y * v.y; ss2 += v.z * v.z; ss3 += v.w * v.w;
            uint32_t p0 = __bfloat16_as_ushort(__float2bfloat16(v.x)) |
                          ((uint32_t)__bfloat16_as_ushort(__float2bfloat16(v.y)) << 16);
            uint32_t p1 = __bfloat16_as_ushort(__float2bfloat16(v.z)) |
                          ((uint32_t)__bfloat16_as_ushort(__float2bfloat16(v.w)) << 16);
            const uint32_t a = (uint32_t)(k << 8) + (((uint32_t)(px4 << 1)) ^ ((k & 7) << 4));
            *(uint2*)(smem + SM_X + a) = make_uint2(p0, p1);
        }
        atomicAdd(&s_n2[px4 + 0], ss0);
        atomicAdd(&s_n2[px4 + 1], ss1);
        atomicAdd(&s_n2[px4 + 2], ss2);
        atomicAdd(&s_n2[px4 + 3], ss3);
    }

    // ---- ldmatrix address precompute ----
    const int lr = lane & 7;
    const int lh = (lane >> 3) & 1;
    const int lq = (lane >> 4) & 1;
    // A (memnorm): mrow(local) = warp_m*64 + mt*16 + lr + lh*8 ; kcol = ks*16 + lq*8
    const uint32_t a_row  = (uint32_t)(warp_m * 64 + lr + lh * 8);
    const uint32_t a_off0 = a_row * 128;
    const uint32_t sw_a   = (a_row & 7) << 4;
    // B (x, trans): krow = kbase + ks*16 + lr + lh*8 ; px = warp_n*32 + nh*16 + lq*8
    const uint32_t krow   = (uint32_t)(lr + lh * 8);
    const uint32_t px2    = (uint32_t)((warp_n * 32 + lq * 8) * 2);
    const uint32_t pxoff0 = px2 ^ ((uint32_t)lr << 4);
    const uint32_t pxoff1 = (px2 + 32) ^ ((uint32_t)lr << 4);

    float d[4][4][4];                    // [mt][nt][reg]
    float rmax[8];                       // running max per col-slot [nt*2+sub]
    int   ridx[8];
    #pragma unroll
    for (int s = 0; s < 8; ++s) { rmax[s] = -3.0e38f; ridx[s] = 0; }

    // ---- mainloop over 64 memnorm tiles (8 chunks x 8 k-tiles) ----
    int buf = 0;
    for (int t = 0; t < NTILES; ++t) {
        if (t + 1 < NTILES) {
            const unsigned char* src = g_membf +
                (size_t)((t + 1) >> 3) * (CHUNK_M * 1024) + (size_t)((t + 1) & 7) * 128;
            const uint32_t dstb = smx + SM_B + (buf ^ 1) * 16384;
            #pragma unroll
            for (int i = 0; i < 4; ++i) {
                const int j = tid + i * 256;
                const int m = j >> 3, g = j & 7;
                cp_async16(dstb + m * 128 + ((g * 16) ^ ((m & 7) * 16)),
                           src + (size_t)m * 1024 + g * 16);
            }
            CP_COMMIT();
            CP_WAIT(1);
        } else {
            CP_WAIT(0);
        }
        __syncthreads();

        if ((t & 7) == 0) {
            #pragma unroll
            for (int mt = 0; mt < 4; ++mt)
                #pragma unroll
                for (int nt = 0; nt < 4; ++nt)
                    #pragma unroll
                    for (int r = 0; r < 4; ++r) d[mt][nt][r] = 0.0f;
        }

        const uint32_t abuf = smx + SM_B + buf * 16384;
        const uint32_t kbase = (uint32_t)((t & 7) * 64);

        #pragma unroll
        for (int ks = 0; ks < 4; ++ks) {
            uint32_t af[4][4];
            #pragma unroll
            for (int mt = 0; mt < 4; ++mt)
                ldsm_x4(af[mt][0], af[mt][1], af[mt][2], af[mt][3],
                        abuf + a_off0 + mt * 2048 + (((uint32_t)(ks * 32 + lq * 16)) ^ sw_a));
            uint32_t bf[8];
            const uint32_t brow = smx + SM_X + (kbase + ks * 16 + krow) * 256;
            ldsm_x4t(bf[0], bf[1], bf[2], bf[3], brow + pxoff0);
            ldsm_x4t(bf[4], bf[5], bf[6], bf[7], brow + pxoff1);
            #pragma unroll
            for (int mt = 0; mt < 4; ++mt)
                #pragma unroll
                for (int nt = 0; nt < 4; ++nt)
                    mma16816(d[mt][nt][0], d[mt][nt][1], d[mt][nt][2], d[mt][nt][3],
                             af[mt][0], af[mt][1], af[mt][2], af[mt][3],
                             bf[nt * 2], bf[nt * 2 + 1]);
        }

        if ((t & 7) == 7) {   // chunk complete: fold into running max (ascending m)
            const int mem_base = (t >> 3) * CHUNK_M + warp_m * 64 + (lane >> 2);
            #pragma unroll
            for (int nt = 0; nt < 4; ++nt)
                #pragma unroll
                for (int sub = 0; sub < 2; ++sub) {
                    const int s = nt * 2 + sub;
                    #pragma unroll
                    for (int mt = 0; mt < 4; ++mt)
                        #pragma unroll
                        for (int rh = 0; rh < 2; ++rh) {
                            const float v = d[mt][nt][rh * 2 + sub];
                            const int mi = mem_base + mt * 16 + rh * 8;
                            if (v > rmax[s]) { rmax[s] = v; ridx[s] = mi; }
                        }
                }
        }
        __syncthreads();
        buf ^= 1;
    }

    // ---- cross-lane reduce (rows live on lanes stride 4) ----
    #pragma unroll
    for (int o = 4; o <= 16; o <<= 1)
        #pragma unroll
        for (int s = 0; s < 8; ++s) {
            const float om = __shfl_xor_sync(0xffffffffu, rmax[s], o);
            const int   oi = __shfl_xor_sync(0xffffffffu, ridx[s], o);
            if (om > rmax[s] || (om == rmax[s] && oi < ridx[s])) { rmax[s] = om; ridx[s] = oi; }
        }
    if (lane < 4) {
        #pragma unroll
        for (int s = 0; s < 8; ++s) {
            const int col = warp_n * 32 + (s >> 1) * 8 + lane * 2 + (s & 1);
            s_rm[warp_m * 128 + col] = rmax[s];
            s_ri[warp_m * 128 + col] = ridx[s];
        }
    }
    __syncthreads();

    // ---- per-pixel decision (flag gray-zone; expected: none) ----
    if (tid < TILE_PX) {
        float bv = s_rm[tid]; int bi = s_ri[tid];
        const float m1 = s_rm[128 + tid]; const int i1 = s_ri[128 + tid];
        if (m1 > bv || (m1 == bv && i1 < bi)) { bv = m1; bi = i1; }
        const float nx = fmaxf(sqrtf(s_n2[tid]), 1e-12f);
        s_flag[tid] = (bv > 0.75f * nx) ? 1 : 0;
        s_pass[tid] = 0;
        s_idx[tid]  = bi;
    }
    __syncthreads();

    // ---- exact fp32 path for flagged pixels (rare; usually skipped) ----
    for (int px = 0; px < TILE_PX; ++px) {
        if (!s_flag[px]) continue;
        for (int c = tid; c < CDIM; c += 256)
            s_xv[c] = x[(size_t)b * CDIM * HWDIM + (size_t)c * HWDIM + n0 + px];
        if (tid == 0) { *s_bestu = 0u; *s_besti = 0x7fffffff; }
        __syncthreads();
        float lb = -3.0e38f; int li = 0x7fffffff;
        #pragma unroll 1
        for (int mm = tid * 4; mm < tid * 4 + 4; ++mm) {
            const float* mr = memory + (size_t)mm * CDIM;
            float dot = 0.f, nn = 0.f;
            for (int c = 0; c < CDIM; ++c) { const float mv = mr[c]; dot += s_xv[c] * mv; nn += mv * mv; }
            const float v = dot / fmaxf(sqrtf(nn), 1e-12f);
            if (v > lb) { lb = v; li = mm; }
        }
        unsigned enc = __float_as_uint(lb);
        enc = (enc & 0x80000000u) ? ~enc : (enc | 0x80000000u);
        atomicMax(s_bestu, enc);
        __syncthreads();
        if (enc == *s_bestu) atomicMin(s_besti, li);
        __syncthreads();
        if (tid == 0) {
            unsigned u = *s_bestu;
            const float bv = __uint_as_float((u & 0x80000000u) ? (u & 0x7fffffffu) : ~u);
            const float nx = fmaxf(sqrtf(s_n2[px]), 1e-12f);
            s_pass[px] = (bv > THRESH * nx) ? 1 : 0;
            s_idx[px]  = *s_besti;
        }
        __syncthreads();
    }
    __syncthreads();

    // ---- writeback: full tile (zeros or gathered memory row), coalesced ----
    {
        const int pxl = tid & 127;
        const int c0  = tid >> 7;
        const int pass = s_pass[pxl];
        const float* mrow = memory + (size_t)s_idx[pxl] * CDIM;
        float* ob = out + (size_t)b * CDIM * HWDIM + n0 + pxl;
        #pragma unroll 8
        for (int c = c0; c < CDIM; c += 2)
            ob[(size_t)c * HWDIM] = pass ? mrow[c] : 0.0f;
    }
}

// ---------------------------------------------------------------------------
extern "C" void kernel_launch(void* const* d_in, const int* in_sizes, int n_in,
                              void* d_out, int out_size) {
    const float* x      = (const float*)d_in[0];
    const float* memory = (const float*)d_in[1];
    float* out          = (float*)d_out;

    cudaFuncSetAttribute(hardmem_main_kernel,
                         cudaFuncAttributeMaxDynamicSharedMemorySize, SM_TOTAL);

    normalize_mem_kernel<<<MMEM, 128>>>(memory);
    hardmem_main_kernel<<<32 * (HWDIM / TILE_PX), 256, SM_TOTAL>>>(x, memory, out);
}